// round 5
// baseline (speedup 1.0000x reference)
#include <cuda_runtime.h>
#include <math.h>

// BidirectionalALiBi: out[h, i, j] = |j - i| * c
//   c = alpha[h] if (i==0 || j==0)
//     else gamma[h] if j > i
//     else beta[h]  if j < i
//     else 0 (diagonal; |j-i|=0 makes it 0 regardless)
//
// Pure HBM-store-bound: 16*2048*2048 fp32 = 256 MiB written.
// Strategy: one row per 512-thread block, each thread writes one float4
// (STG.128, fully coalesced). Branch-free selects per lane.

__global__ __launch_bounds__(512, 4)
void alibi_vec4_kernel(const float* __restrict__ alpha,
                       const float* __restrict__ beta,
                       const float* __restrict__ gamma,
                       float* __restrict__ out,
                       int S)
{
    const int row = blockIdx.x;       // 0 .. H*S-1
    const int h   = row / S;
    const int i   = row - h * S;

    const float a = __ldg(alpha + h);
    const float b = __ldg(beta  + h);
    const float g = __ldg(gamma + h);

    float4* __restrict__ orow =
        reinterpret_cast<float4*>(out + (size_t)row * (size_t)S);

    const int nvec = S >> 2;          // S/4 float4 per row
    for (int t = threadIdx.x; t < nvec; t += blockDim.x) {
        const int j0 = t << 2;
        float4 v;
        float* vp = reinterpret_cast<float*>(&v);
#pragma unroll
        for (int k = 0; k < 4; k++) {
            const int j = j0 + k;
            // select coefficient (SEL chain, no divergence)
            float c = (j > i) ? g : b;        // upper vs lower
            c = (i == 0 || j == 0) ? a : c;   // edge overrides
            // diagonal: dist = 0 -> value 0 regardless of c
            const float dist = fabsf((float)(j - i));
            vp[k] = dist * c;
        }
        orow[t] = v;                  // STG.E.128
    }
}

// Scalar fallback for S not divisible by 4 (not expected for S=2048, but safe).
__global__ void alibi_scalar_kernel(const float* __restrict__ alpha,
                                    const float* __restrict__ beta,
                                    const float* __restrict__ gamma,
                                    float* __restrict__ out,
                                    int S, int H)
{
    const long long total = (long long)H * S * S;
    for (long long idx = (long long)blockIdx.x * blockDim.x + threadIdx.x;
         idx < total;
         idx += (long long)gridDim.x * blockDim.x)
    {
        const int j = (int)(idx % S);
        long long r = idx / S;
        const int i = (int)(r % S);
        const int h = (int)(r / S);
        float c = (j > i) ? __ldg(gamma + h) : __ldg(beta + h);
        c = (i == 0 || j == 0) ? __ldg(alpha + h) : c;
        out[idx] = fabsf((float)(j - i)) * c;
    }
}

extern "C" void kernel_launch(void* const* d_in, const int* in_sizes, int n_in,
                              void* d_out, int out_size)
{
    const float* alpha = (const float*)d_in[0];
    const float* beta  = (const float*)d_in[1];
    const float* gamma = (const float*)d_in[2];
    // d_in[3] is seq_len on device; reading it would require a sync (not
    // graph-capturable). Derive S from out_size: out_size = H * S * S.
    const int H = in_sizes[0];
    float* out = (float*)d_out;

    // integer sqrt of out_size / H
    long long per_h = (long long)out_size / H;
    long long s = (long long)(sqrt((double)per_h));
    while (s * s < per_h) s++;
    while (s * s > per_h) s--;
    const int S = (int)s;

    if ((S & 3) == 0 && S >= 4) {
        const int rows = H * S;
        alibi_vec4_kernel<<<rows, 512>>>(alpha, beta, gamma, out, S);
    } else {
        const long long total = (long long)H * S * S;
        int blocks = (int)((total + 255) / 256);
        if (blocks > 148 * 32 * 4) blocks = 148 * 32 * 4;
        alibi_scalar_kernel<<<blocks, 256>>>(alpha, beta, gamma, out, S, H);
    }
}

// round 8
// speedup vs baseline: 1.8465x; 1.8465x over previous
#include <cuda_runtime.h>
#include <math.h>

// BidirectionalALiBi: out[h, i, j] = |j - i| * c
//   c = alpha[h] if (i==0 || j==0), gamma[h] if j>i, beta[h] if j<i, 0 on diag.
//
// Branch-free identity: with p=(g+b)/2, m=(g-b)/2, d=j-i (float):
//   |d|*p + d*m  =  d*g (d>0) | |d|*b (d<0) | 0 (d==0)
// Row i==0 -> set g=b=alpha (then |d|*a = j*a, correct incl. j=0).
// Column j==0 -> single patched element per row: i*alpha.
//
// Layout: 512-thread block covers 8 consecutive rows (64 threads/row),
// each thread writes 8 float4 strided by 64 float4 so every warp STG.128
// covers 512B contiguous. All indexing is shifts (S compile-time).

template<int LOGS>
__global__ __launch_bounds__(512, 2)
void alibi_tiled_kernel(const float* __restrict__ alpha,
                        const float* __restrict__ beta,
                        const float* __restrict__ gamma,
                        float* __restrict__ out)
{
    constexpr int S     = 1 << LOGS;
    constexpr int VROW  = S >> 2;        // float4 per row
    constexpr int NITER = VROW >> 6;     // 8 when S=2048 (64 threads/row)

    const int tid     = threadIdx.x;
    const int r_local = tid >> 6;                 // 0..7
    const int trow    = tid & 63;                 // 0..63 within row
    const int row     = (blockIdx.x << 3) + r_local;
    const int h       = row >> LOGS;              // 8 rows/block share h (S%8==0)
    const int i       = row & (S - 1);

    float a = __ldg(alpha + h);
    float b = __ldg(beta  + h);
    float g = __ldg(gamma + h);
    if (i == 0) { g = a; b = a; }                 // whole-row edge override

    const float p  = 0.5f * (g + b);
    const float m  = 0.5f * (g - b);
    const float fi = (float)i;
    const float d0 = (float)(trow << 2) - fi;     // d for (v=0, k=0)
    const bool  patch_j0 = (trow == 0);           // j==0 column owner

    float4* __restrict__ orow =
        reinterpret_cast<float4*>(out) + (size_t)row * VROW + trow;

    // First iteration (may contain the j==0 patch), then the clean tail.
    {
        float4 w;
        w.x = patch_j0 ? fi * a
                       : fmaf(fabsf(d0        ), p, (d0        ) * m);
        w.y = fmaf(fabsf(d0 + 1.0f), p, (d0 + 1.0f) * m);
        w.z = fmaf(fabsf(d0 + 2.0f), p, (d0 + 2.0f) * m);
        w.w = fmaf(fabsf(d0 + 3.0f), p, (d0 + 3.0f) * m);
        orow[0] = w;                              // STG.E.128
    }
#pragma unroll
    for (int v = 1; v < NITER; v++) {
        const float dv = d0 + (float)(v << 8);    // stride 64 float4 = 256 floats
        float4 w;
        w.x = fmaf(fabsf(dv        ), p, (dv        ) * m);
        w.y = fmaf(fabsf(dv + 1.0f), p, (dv + 1.0f) * m);
        w.z = fmaf(fabsf(dv + 2.0f), p, (dv + 2.0f) * m);
        w.w = fmaf(fabsf(dv + 3.0f), p, (dv + 3.0f) * m);
        orow[(size_t)(v << 6)] = w;               // STG.E.128, warp-contiguous
    }
}

// Generic fallback for arbitrary S (kept correct, not perf-critical).
__global__ void alibi_scalar_kernel(const float* __restrict__ alpha,
                                    const float* __restrict__ beta,
                                    const float* __restrict__ gamma,
                                    float* __restrict__ out,
                                    int S, int H)
{
    const long long total = (long long)H * S * S;
    for (long long idx = (long long)blockIdx.x * blockDim.x + threadIdx.x;
         idx < total;
         idx += (long long)gridDim.x * blockDim.x)
    {
        const int j = (int)(idx % S);
        long long r = idx / S;
        const int i = (int)(r % S);
        const int h = (int)(r / S);
        float c = (j > i) ? __ldg(gamma + h) : __ldg(beta + h);
        c = (i == 0 || j == 0) ? __ldg(alpha + h) : c;
        out[idx] = fabsf((float)(j - i)) * c;
    }
}

extern "C" void kernel_launch(void* const* d_in, const int* in_sizes, int n_in,
                              void* d_out, int out_size)
{
    const float* alpha = (const float*)d_in[0];
    const float* beta  = (const float*)d_in[1];
    const float* gamma = (const float*)d_in[2];
    const int H = in_sizes[0];
    float* out = (float*)d_out;

    // Derive S from out_size = H*S*S (seq_len lives on device; can't sync-read
    // under graph capture).
    long long per_h = (long long)out_size / H;
    long long s = (long long)(sqrt((double)per_h));
    while (s * s < per_h) s++;
    while (s * s > per_h) s--;
    const int S = (int)s;

    if (S == 2048) {
        const int blocks = (H * S) >> 3;          // 8 rows per block
        alibi_tiled_kernel<11><<<blocks, 512>>>(alpha, beta, gamma, out);
    } else if (S == 1024) {
        const int blocks = (H * S) >> 3;
        alibi_tiled_kernel<10><<<blocks, 512>>>(alpha, beta, gamma, out);
    } else if (S == 4096) {
        const int blocks = (H * S) >> 3;
        alibi_tiled_kernel<12><<<blocks, 512>>>(alpha, beta, gamma, out);
    } else {
        const long long total = (long long)H * S * S;
        int blocks = (int)((total + 255) / 256);
        if (blocks > 148 * 32 * 4) blocks = 148 * 32 * 4;
        alibi_scalar_kernel<<<blocks, 256>>>(alpha, beta, gamma, out, S, H);
    }
}